// round 1
// baseline (speedup 1.0000x reference)
#include <cuda_runtime.h>
#include <math.h>

#define NNODE 4095
#define HID   768
#define INP   300
#define NWAVE 24
#define MAXW  1152

#define BM   64
#define BK   16
#define BNG  64
#define BN   192      // 3 gate groups x 64 cols
#define NTHR 256
#define AP   (BM+4)   // padded As row (keeps 16B alignment)

// ---------------- device scratch (no allocations allowed) ----------------
__device__ float d_H[NNODE*HID];
__device__ float d_C[NNODE*HID];
__device__ float d_LH[NNODE*HID];   // leaf-LSTM hidden (hc for leaves)
__device__ float d_LC[NNODE*HID];   // leaf-LSTM cell
__device__ int   d_done[NNODE];
__device__ int   d_listB[NWAVE*MAXW];   // nodes with prev>=0 (K=1536)
__device__ int   d_listC[NWAVE*MAXW];   // nodes with prev<0  (K=768, Wc only)
__device__ int   d_nb[NWAVE];
__device__ int   d_nc[NWAVE];
__device__ int   d_leaf[NNODE];
__device__ int   d_nleaf;

// ---------------- tiny control kernels ----------------
__global__ void reset_kernel() {
    int i = blockIdx.x*blockDim.x + threadIdx.x;
    if (i < NNODE) d_done[i] = 0;
    if (i < NWAVE) { d_nb[i] = 0; d_nc[i] = 0; }
    if (i == 0) d_nleaf = 0;
}

__global__ void leaflist_kernel(const int* __restrict__ leaf_mask) {
    int i = blockIdx.x*blockDim.x + threadIdx.x;
    if (i < NNODE && leaf_mask[i]) {
        int p = atomicAdd(&d_nleaf, 1);
        if (p < NNODE) d_leaf[p] = i;
    }
}

__global__ void collect_kernel(const int* __restrict__ leaf_mask,
                               const int* __restrict__ child_idx,
                               const int* __restrict__ prev_idx, int w) {
    int i = blockIdx.x*blockDim.x + threadIdx.x;
    if (i >= NNODE) return;
    if (d_done[i]) return;
    int pi = prev_idx[i];
    if (pi >= 0 && !d_done[pi]) return;
    if (!leaf_mask[i] && !d_done[child_idx[i]]) return;
    if (pi < 0) {
        int p = atomicAdd(&d_nc[w], 1);
        if (p < MAXW) d_listC[w*MAXW + p] = i;
    } else {
        int p = atomicAdd(&d_nb[w], 1);
        if (p < MAXW) d_listB[w*MAXW + p] = i;
    }
}

__global__ void copyout_kernel(float* __restrict__ out, int out_size) {
    int j = blockIdx.x*blockDim.x + threadIdx.x;
    if (j < HID && j < out_size) out[j] = d_H[(size_t)(NNODE-1)*HID + j];
}

// ---------------- leaf GEMM + gates ----------------
// g4 = emb[word] @ Wx^T + bx + bh ; i,o,f,c chunks; cell=sig(i)*tanh(c); hid=sig(o)*tanh(cell)
__global__ __launch_bounds__(NTHR)
void leaf_kernel(const int* __restrict__ word,
                 const float* __restrict__ emb,
                 const float* __restrict__ Wx,
                 const float* __restrict__ bx,
                 const float* __restrict__ bh)
{
    __shared__ float smem[BK*AP + BK*BN];
    float* As = smem;
    float* Bs = smem + BK*AP;
    __shared__ const float* s_x[BM];
    __shared__ int s_node[BM];

    int nl = d_nleaf;
    int base = blockIdx.x * BM;
    if (base >= nl) return;
    int rows = min(BM, nl - base);
    int tid = threadIdx.x;
    int jt = blockIdx.y;

    if (tid < BM) {
        if (tid < rows) {
            int node = d_leaf[base + tid];
            s_node[tid] = node;
            s_x[tid] = emb + (size_t)word[node] * INP;
        } else { s_node[tid] = -1; s_x[tid] = 0; }
    }
    __syncthreads();

    float acc[8][6];
    #pragma unroll
    for (int r = 0; r < 8; r++)
        #pragma unroll
        for (int c = 0; c < 6; c++) acc[r][c] = 0.f;

    int tmg = tid >> 5;       // 0..7  rows tmg*8..+7
    int tng = tid & 31;       // cols tng*6..+5
    int lm  = tid >> 2;       // 0..63
    int lk  = (tid & 3) * 4;  // k offset

    for (int k0 = 0; k0 < INP; k0 += BK) {
        {
            const float* rp = s_x[lm];
            #pragma unroll
            for (int j = 0; j < 4; j++) {
                int k = k0 + lk + j;
                As[(lk+j)*AP + lm] = (rp && k < INP) ? rp[k] : 0.f;
            }
        }
        #pragma unroll
        for (int pass = 0; pass < 3; pass++) {
            int n = pass*64 + lm;
            int g = n >> 6, col = n & 63;
            int jp = (g == 0 ? 0 : (g == 1 ? HID : 3*HID)) + jt*BNG + col; // i,o,c groups
            #pragma unroll
            for (int j = 0; j < 4; j++) {
                int k = k0 + lk + j;
                Bs[(lk+j)*BN + n] = (k < INP) ? Wx[(size_t)jp*INP + k] : 0.f;
            }
        }
        __syncthreads();
        #pragma unroll
        for (int k = 0; k < BK; k++) {
            float a[8], b[6];
            float4 a0 = *reinterpret_cast<const float4*>(&As[k*AP + tmg*8]);
            float4 a1 = *reinterpret_cast<const float4*>(&As[k*AP + tmg*8 + 4]);
            a[0]=a0.x; a[1]=a0.y; a[2]=a0.z; a[3]=a0.w;
            a[4]=a1.x; a[5]=a1.y; a[6]=a1.z; a[7]=a1.w;
            #pragma unroll
            for (int c = 0; c < 6; c++) b[c] = Bs[k*BN + tng*6 + c];
            #pragma unroll
            for (int r = 0; r < 8; r++)
                #pragma unroll
                for (int c = 0; c < 6; c++)
                    acc[r][c] += a[r]*b[c];
        }
        __syncthreads();
    }

    float* Gs = smem;  // 16 x 192 slab
    for (int s = 0; s < 4; s++) {
        if ((tmg >> 1) == s) {
            int rl = (tmg & 1) * 8;
            #pragma unroll
            for (int r = 0; r < 8; r++)
                #pragma unroll
                for (int c = 0; c < 6; c++)
                    Gs[(rl+r)*BN + tng*6 + c] = acc[r][c];
        }
        __syncthreads();
        for (int it = tid; it < 16*BNG; it += NTHR) {
            int r = it >> 6, j = it & 63, m = s*16 + r;
            if (m < rows) {
                int jg = jt*BNG + j;
                float gi = Gs[r*BN + j]       + bx[jg]        + bh[jg];
                float go = Gs[r*BN + 64 + j]  + bx[HID+jg]    + bh[HID+jg];
                float gc = Gs[r*BN + 128 + j] + bx[3*HID+jg]  + bh[3*HID+jg];
                float si = 1.f/(1.f + expf(-gi));
                float so = 1.f/(1.f + expf(-go));
                float cell = si * tanhf(gc);
                float hidv = so * tanhf(cell);
                int node = s_node[m];
                d_LC[(size_t)node*HID + jg] = cell;
                d_LH[(size_t)node*HID + jg] = hidv;
            }
        }
        __syncthreads();
    }
}

// ---------------- wave combine GEMM + gates ----------------
// g = hx@Ws^T + bs + hc@Wc^T + bc ; i,o,f chunks; cell=sig(f)*cx+sig(i)*cc; hid=sig(o)*tanh(cell)
__global__ __launch_bounds__(NTHR)
void combine_kernel(const int* __restrict__ leaf_mask,
                    const int* __restrict__ child_idx,
                    const int* __restrict__ prev_idx,
                    const float* __restrict__ Ws, const float* __restrict__ bs,
                    const float* __restrict__ Wc, const float* __restrict__ bc,
                    int w)
{
    __shared__ float smem[BK*AP + BK*BN];
    float* As = smem;
    float* Bs = smem + BK*AP;
    __shared__ const float* s_hx[BM];
    __shared__ const float* s_hc[BM];
    __shared__ const float* s_cx[BM];
    __shared__ const float* s_cc[BM];
    __shared__ int s_node[BM];

    int nb = d_nb[w], nc = d_nc[w];
    if (nb > MAXW) nb = MAXW;
    if (nc > MAXW) nc = MAXW;
    int nbt = (nb + BM - 1) / BM;
    int nct = (nc + BM - 1) / BM;
    int bxi = blockIdx.x;
    if (bxi >= nbt + nct) return;

    bool conly; const int* list; int base, cnt;
    if (bxi < nbt) { conly = false; list = d_listB + w*MAXW; base = bxi*BM;       cnt = nb; }
    else           { conly = true;  list = d_listC + w*MAXW; base = (bxi-nbt)*BM; cnt = nc; }
    int rows = min(BM, cnt - base);
    int tid = threadIdx.x;
    int jt = blockIdx.y;   // 0..11

    if (tid < BM) {
        if (tid < rows) {
            int node = list[base + tid];
            s_node[tid] = node;
            int pi = prev_idx[node];
            s_hx[tid] = (pi >= 0) ? d_H + (size_t)pi*HID : 0;
            s_cx[tid] = (pi >= 0) ? d_C + (size_t)pi*HID : 0;
            if (leaf_mask[node]) {
                s_hc[tid] = d_LH + (size_t)node*HID;
                s_cc[tid] = d_LC + (size_t)node*HID;
            } else {
                int ci = child_idx[node];
                s_hc[tid] = d_H + (size_t)ci*HID;
                s_cc[tid] = d_C + (size_t)ci*HID;
            }
        } else {
            s_node[tid] = -1; s_hx[tid] = 0; s_hc[tid] = 0; s_cx[tid] = 0; s_cc[tid] = 0;
        }
    }
    __syncthreads();

    float acc[8][6];
    #pragma unroll
    for (int r = 0; r < 8; r++)
        #pragma unroll
        for (int c = 0; c < 6; c++) acc[r][c] = 0.f;

    int tmg = tid >> 5;
    int tng = tid & 31;
    int lm  = tid >> 2;
    int lk  = (tid & 3) * 4;

    for (int phase = conly ? 1 : 0; phase < 2; phase++) {
        const float* Bmat = phase ? Wc : Ws;
        for (int k0 = 0; k0 < HID; k0 += BK) {
            {
                const float* rp = phase ? s_hc[lm] : s_hx[lm];
                float4 v = make_float4(0.f, 0.f, 0.f, 0.f);
                if (rp) v = *reinterpret_cast<const float4*>(rp + k0 + lk);
                As[(lk+0)*AP + lm] = v.x;
                As[(lk+1)*AP + lm] = v.y;
                As[(lk+2)*AP + lm] = v.z;
                As[(lk+3)*AP + lm] = v.w;
            }
            #pragma unroll
            for (int pass = 0; pass < 3; pass++) {
                int n = pass*64 + lm;
                int g = n >> 6, col = n & 63;
                int jp = g*HID + jt*BNG + col;   // row of Ws/Wc (3H x H)
                float4 v = *reinterpret_cast<const float4*>(Bmat + (size_t)jp*HID + k0 + lk);
                Bs[(lk+0)*BN + n] = v.x;
                Bs[(lk+1)*BN + n] = v.y;
                Bs[(lk+2)*BN + n] = v.z;
                Bs[(lk+3)*BN + n] = v.w;
            }
            __syncthreads();
            #pragma unroll
            for (int k = 0; k < BK; k++) {
                float a[8], b[6];
                float4 a0 = *reinterpret_cast<const float4*>(&As[k*AP + tmg*8]);
                float4 a1 = *reinterpret_cast<const float4*>(&As[k*AP + tmg*8 + 4]);
                a[0]=a0.x; a[1]=a0.y; a[2]=a0.z; a[3]=a0.w;
                a[4]=a1.x; a[5]=a1.y; a[6]=a1.z; a[7]=a1.w;
                #pragma unroll
                for (int c = 0; c < 6; c++) b[c] = Bs[k*BN + tng*6 + c];
                #pragma unroll
                for (int r = 0; r < 8; r++)
                    #pragma unroll
                    for (int c = 0; c < 6; c++)
                        acc[r][c] += a[r]*b[c];
            }
            __syncthreads();
        }
    }

    float* Gs = smem;  // 16 x 192 slab
    for (int s = 0; s < 4; s++) {
        if ((tmg >> 1) == s) {
            int rl = (tmg & 1) * 8;
            #pragma unroll
            for (int r = 0; r < 8; r++)
                #pragma unroll
                for (int c = 0; c < 6; c++)
                    Gs[(rl+r)*BN + tng*6 + c] = acc[r][c];
        }
        __syncthreads();
        for (int it = tid; it < 16*BNG; it += NTHR) {
            int r = it >> 6, j = it & 63, m = s*16 + r;
            if (m < rows) {
                int jg = jt*BNG + j;
                float gi = Gs[r*BN + j]       + bs[jg]       + bc[jg];
                float go = Gs[r*BN + 64 + j]  + bs[HID+jg]   + bc[HID+jg];
                float gf = Gs[r*BN + 128 + j] + bs[2*HID+jg] + bc[2*HID+jg];
                float cx = s_cx[m] ? s_cx[m][jg] : 0.f;
                float cc = s_cc[m][jg];
                float si = 1.f/(1.f + expf(-gi));
                float so = 1.f/(1.f + expf(-go));
                float sf = 1.f/(1.f + expf(-gf));
                float cell = sf*cx + si*cc;
                float hidv = so * tanhf(cell);
                int node = s_node[m];
                d_C[(size_t)node*HID + jg] = cell;
                d_H[(size_t)node*HID + jg] = hidv;
            }
        }
        __syncthreads();
    }

    if (jt == 0 && tid < rows) d_done[s_node[tid]] = 1;
}

// ---------------- launch ----------------
extern "C" void kernel_launch(void* const* d_in, const int* in_sizes, int n_in,
                              void* d_out, int out_size) {
    const int* leaf_mask = (const int*)d_in[0];
    const int* word      = (const int*)d_in[1];
    const int* child_idx = (const int*)d_in[2];
    const int* prev_idx  = (const int*)d_in[3];
    const float* emb = (const float*)d_in[4];
    const float* Wx  = (const float*)d_in[5];
    const float* bx  = (const float*)d_in[6];
    // d_in[7] = Wh (unused by the reference math: encode_h(0) contributes only bh)
    const float* bh  = (const float*)d_in[8];
    const float* Ws  = (const float*)d_in[9];
    const float* bs  = (const float*)d_in[10];
    const float* Wc  = (const float*)d_in[11];
    const float* bc  = (const float*)d_in[12];

    reset_kernel<<<16, 256>>>();
    leaflist_kernel<<<16, 256>>>(leaf_mask);
    leaf_kernel<<<dim3((NNODE + BM - 1)/BM, 12), NTHR>>>(word, emb, Wx, bx, bh);
    for (int w = 0; w < NWAVE; w++) {
        collect_kernel<<<16, 256>>>(leaf_mask, child_idx, prev_idx, w);
        combine_kernel<<<dim3((NNODE + BM - 1)/BM, 12), NTHR>>>(
            leaf_mask, child_idx, prev_idx, Ws, bs, Wc, bc, w);
    }
    copyout_kernel<<<3, 256>>>((float*)d_out, out_size);
}

// round 7
// speedup vs baseline: 1.9137x; 1.9137x over previous
#include <cuda_runtime.h>
#include <math.h>

#define NNODE 4095
#define HID   768
#define GC    2304      // 3*HID gate columns
#define KTOT  1536      // [hx | hc]
#define NWAVE 34
#define MAXW  1280
#define GRID  148
#define NTHR  256
#define KSROWS 512

// leaf-kernel tile params
#define LBM   64
#define LBK   16
#define LBNG  64
#define LBN   192
#define LAP   (LBM+4)

// ---------------- device scratch ----------------
__device__ float d_H[NNODE*HID];
__device__ float d_C[NNODE*HID];
__device__ float d_LH[NNODE*HID];
__device__ float d_LC[NNODE*HID];
__device__ float d_Wsc[(size_t)GC*KTOT];   // [2304][1536]: k<768 -> Ws, k>=768 -> Wc
__device__ float d_bsc[GC];
__device__ float d_G[(size_t)MAXW*GC];
__device__ float d_Gx[(size_t)7*KSROWS*GC];
__device__ int   d_listB[NWAVE*MAXW];
__device__ int   d_listC[NWAVE*MAXW];
__device__ int   d_nb[NWAVE];
__device__ int   d_nc[NWAVE];
__device__ int   d_deps[NNODE];
__device__ int   d_nextsib[NNODE];
__device__ int   d_parlast[NNODE];
__device__ int   d_leafarr[NNODE];
__device__ int   d_nleaf;
__device__ unsigned g_cnt;
__device__ volatile unsigned g_gen;

// ---------------- grid barrier (all GRID blocks co-resident) ----------------
__device__ __forceinline__ void gbar() {
    __syncthreads();
    if (threadIdx.x == 0) {
        unsigned g = g_gen;
        __threadfence();
        if (atomicAdd(&g_cnt, 1u) == GRID - 1) {
            g_cnt = 0;
            __threadfence();
            g_gen = g + 1;
        } else {
            while (g_gen == g) { __nanosleep(32); }
        }
        __threadfence();
    }
    __syncthreads();
}

// ---------------- prep kernels ----------------
__global__ void prep1(const float* __restrict__ Ws, const float* __restrict__ Wc,
                      const float* __restrict__ bs, const float* __restrict__ bc) {
    long i0 = (long)blockIdx.x * blockDim.x + threadIdx.x;
    long stride = (long)gridDim.x * blockDim.x;
    for (long t = i0; t < (long)GC * KTOT; t += stride) {
        int j = (int)(t / KTOT), k = (int)(t % KTOT);
        d_Wsc[t] = (k < HID) ? Ws[(size_t)j * HID + k] : Wc[(size_t)j * HID + (k - HID)];
    }
    for (long t = i0; t < GC; t += stride) d_bsc[t] = bs[t] + bc[t];
    for (long t = i0; t < NNODE; t += stride) { d_nextsib[t] = -1; d_parlast[t] = -1; }
    for (long t = i0; t < NWAVE; t += stride) { d_nb[t] = 0; d_nc[t] = 0; }
    if (i0 == 0) { d_nleaf = 0; g_cnt = 0; g_gen = 0; }
}

__global__ void prep2(const int* __restrict__ leaf_mask,
                      const int* __restrict__ child_idx,
                      const int* __restrict__ prev_idx) {
    int i = blockIdx.x * blockDim.x + threadIdx.x;
    if (i >= NNODE) return;
    int pi = prev_idx[i];
    int isleaf = leaf_mask[i];
    d_deps[i] = (pi >= 0 ? 1 : 0) + (isleaf ? 0 : 1);
    if (pi >= 0) d_nextsib[pi] = i;
    if (!isleaf) d_parlast[child_idx[i]] = i;
    if (isleaf) { int s = atomicAdd(&d_nleaf, 1); if (s < NNODE) d_leafarr[s] = i; }
    if (pi < 0 && isleaf) { int s = atomicAdd(&d_nc[0], 1); if (s < MAXW) d_listC[s] = i; }
}

__global__ void copyout_kernel(float* __restrict__ out, int out_size) {
    int j = blockIdx.x * blockDim.x + threadIdx.x;
    if (j < HID && j < out_size) out[j] = d_H[(size_t)(NNODE - 1) * HID + j];
}

// ---------------- leaf GEMM + gates ----------------
__global__ __launch_bounds__(NTHR)
void leaf_kernel(const int* __restrict__ word,
                 const float* __restrict__ emb,
                 const float* __restrict__ Wx,
                 const float* __restrict__ bx,
                 const float* __restrict__ bh)
{
    __shared__ float smem[LBK*LAP + LBK*LBN];
    float* As = smem;
    float* Bs = smem + LBK*LAP;
    __shared__ const float* s_x[LBM];
    __shared__ int s_node[LBM];

    int nl = d_nleaf;
    int base = blockIdx.x * LBM;
    if (base >= nl) return;
    int rows = min(LBM, nl - base);
    int tid = threadIdx.x;
    int jt = blockIdx.y;

    if (tid < LBM) {
        if (tid < rows) {
            int node = d_leafarr[base + tid];
            s_node[tid] = node;
            s_x[tid] = emb + (size_t)word[node] * 300;
        } else { s_node[tid] = -1; s_x[tid] = 0; }
    }
    __syncthreads();

    float acc[8][6];
    #pragma unroll
    for (int r = 0; r < 8; r++)
        #pragma unroll
        for (int c = 0; c < 6; c++) acc[r][c] = 0.f;

    int tmg = tid >> 5;
    int tng = tid & 31;
    int lm  = tid >> 2;
    int lk  = (tid & 3) * 4;

    for (int k0 = 0; k0 < 300; k0 += LBK) {
        {
            const float* rp = s_x[lm];
            #pragma unroll
            for (int j = 0; j < 4; j++) {
                int k = k0 + lk + j;
                As[(lk+j)*LAP + lm] = (rp && k < 300) ? rp[k] : 0.f;
            }
        }
        #pragma unroll
        for (int pass = 0; pass < 3; pass++) {
            int n = pass*64 + lm;
            int g = n >> 6, col = n & 63;
            int jp = (g == 0 ? 0 : (g == 1 ? HID : 3*HID)) + jt*LBNG + col;
            #pragma unroll
            for (int j = 0; j < 4; j++) {
                int k = k0 + lk + j;
                Bs[(lk+j)*LBN + n] = (k < 300) ? Wx[(size_t)jp*300 + k] : 0.f;
            }
        }
        __syncthreads();
        #pragma unroll
        for (int k = 0; k < LBK; k++) {
            float a[8], b[6];
            float4 a0 = *reinterpret_cast<const float4*>(&As[k*LAP + tmg*8]);
            float4 a1 = *reinterpret_cast<const float4*>(&As[k*LAP + tmg*8 + 4]);
            a[0]=a0.x; a[1]=a0.y; a[2]=a0.z; a[3]=a0.w;
            a[4]=a1.x; a[5]=a1.y; a[6]=a1.z; a[7]=a1.w;
            #pragma unroll
            for (int c = 0; c < 6; c++) b[c] = Bs[k*LBN + tng*6 + c];
            #pragma unroll
            for (int r = 0; r < 8; r++)
                #pragma unroll
                for (int c = 0; c < 6; c++)
                    acc[r][c] += a[r]*b[c];
        }
        __syncthreads();
    }

    float* Gs = smem;
    for (int s = 0; s < 4; s++) {
        if ((tmg >> 1) == s) {
            int rl = (tmg & 1) * 8;
            #pragma unroll
            for (int r = 0; r < 8; r++)
                #pragma unroll
                for (int c = 0; c < 6; c++)
                    Gs[(rl+r)*LBN + tng*6 + c] = acc[r][c];
        }
        __syncthreads();
        for (int it = tid; it < 16*LBNG; it += NTHR) {
            int r = it >> 6, j = it & 63, m = s*16 + r;
            if (m < rows) {
                int jg = jt*LBNG + j;
                float gi = Gs[r*LBN + j]       + bx[jg]        + bh[jg];
                float go = Gs[r*LBN + 64 + j]  + bx[HID+jg]    + bh[HID+jg];
                float gc = Gs[r*LBN + 128 + j] + bx[3*HID+jg]  + bh[3*HID+jg];
                float si = 1.f/(1.f + expf(-gi));
                float so = 1.f/(1.f + expf(-go));
                float cell = si * tanhf(gc);
                float hidv = so * tanhf(cell);
                int node = s_node[m];
                d_LC[(size_t)node*HID + jg] = cell;
                d_LH[(size_t)node*HID + jg] = hidv;
            }
        }
        __syncthreads();
    }
}

// ---------------- persistent wave kernel ----------------
__global__ __launch_bounds__(NTHR, 1)
void persist_kernel(const int* __restrict__ leaf_mask,
                    const int* __restrict__ child_idx,
                    const int* __restrict__ prev_idx)
{
    __shared__ float As[16*128];
    __shared__ float Bs[16*128];
    __shared__ const float* s_pl[128];
    __shared__ const float* s_ph[128];

    int tid = threadIdx.x, bid = blockIdx.x;
    int lane = tid & 31, wid = tid >> 5;

    for (int w = 0; w < NWAVE - 1; w++) {
        gbar();
        int nb = min(d_nb[w], MAXW), nc = min(d_nc[w], MAXW);
        int rows = nb + nc;
        if (rows == 0) break;

        bool big = rows > 192;
        int BMc = big ? 128 : 64;
        int rtB = (nb + BMc - 1) / BMc, rtC = (nc + BMc - 1) / BMc;
        int tiles0 = (rtB + rtC) * 18;
        int ks = 1;
        while (ks < 8 && tiles0 * ks < 120) ks <<= 1;
        if (rows > KSROWS) ks = 1;
        int ntiles = tiles0 * ks;

        for (int t = bid; t < ntiles; t += GRID) {
            int part = t % ks; int tmp = t / ks; int jt = tmp % 18; int rt = tmp / 18;
            const int* list; int base, cnt, r0, klen, kbeg;
            if (rt < rtB) { list = d_listB + w*MAXW; base = rt*BMc;       cnt = nb; r0 = base;      klen = KTOT/ks; kbeg = part*klen; }
            else          { list = d_listC + w*MAXW; base = (rt-rtB)*BMc; cnt = nc; r0 = nb + base; klen = HID/ks;  kbeg = HID + part*klen; }
            int rows_t = min(BMc, cnt - base);

            __syncthreads();  // protect smem reuse between tiles
            for (int i = tid; i < BMc; i += NTHR) {
                if (i < rows_t) {
                    int node = list[base + i];
                    int pi = prev_idx[node];
                    s_pl[i] = (pi >= 0) ? d_H + (size_t)pi * HID : 0;
                    s_ph[i] = leaf_mask[node] ? d_LH + (size_t)node * HID
                                              : d_H + (size_t)child_idx[node] * HID;
                } else { s_pl[i] = 0; s_ph[i] = 0; }
            }
            __syncthreads();

            if (big) {
                int ty = tid >> 4, tx = tid & 15;
                float acc[8][8];
                #pragma unroll
                for (int r = 0; r < 8; r++)
                    #pragma unroll
                    for (int c = 0; c < 8; c++) acc[r][c] = 0.f;
                int lmA = tid & 127, khA = (tid >> 7) * 8;
                int jloc = tid >> 1;
                int jB = jt*128 + jloc, kqB = (tid & 1) * 8;

                for (int kc = kbeg; kc < kbeg + klen; kc += 16) {
                    const float* p = (kc < HID) ? s_pl[lmA] : s_ph[lmA];
                    int ko = (kc < HID) ? kc : kc - HID;
                    float4 v0 = make_float4(0.f,0.f,0.f,0.f), v1 = v0;
                    if (p) {
                        v0 = *reinterpret_cast<const float4*>(p + ko + khA);
                        v1 = *reinterpret_cast<const float4*>(p + ko + khA + 4);
                    }
                    As[(khA+0)*128 + lmA] = v0.x; As[(khA+1)*128 + lmA] = v0.y;
                    As[(khA+2)*128 + lmA] = v0.z; As[(khA+3)*128 + lmA] = v0.w;
                    As[(khA+4)*128 + lmA] = v1.x; As[(khA+5)*128 + lmA] = v1.y;
                    As[(khA+6)*128 + lmA] = v1.z; As[(khA+7)*128 + lmA] = v1.w;

                    const float* wp = d_Wsc + (size_t)jB * KTOT + kc + kqB;
                    float4 w0 = *reinterpret_cast<const float4*>(wp);
                    float4 w1 = *reinterpret_cast<const float4*>(wp + 4);
                    Bs[(kqB+0)*128 + jloc] = w0.x; Bs[(kqB+1)*128 + jloc] = w0.y;
                    Bs[(kqB+2)*128 + jloc] = w0.z; Bs[(kqB+3)*128 + jloc] = w0.w;
                    Bs[(kqB+4)*128 + jloc] = w1.x; Bs[(kqB+5)*128 + jloc] = w1.y;
                    Bs[(kqB+6)*128 + jloc] = w1.z; Bs[(kqB+7)*128 + jloc] = w1.w;
                    __syncthreads();
                    #pragma unroll
                    for (int k = 0; k < 16; k++) {
                        float4 a0 = *reinterpret_cast<const float4*>(&As[k*128 + ty*8]);
                        float4 a1 = *reinterpret_cast<const float4*>(&As[k*128 + ty*8 + 4]);
                        float4 b0 = *reinterpret_cast<const float4*>(&Bs[k*128 + tx*8]);
                        float4 b1 = *reinterpret_cast<const float4*>(&Bs[k*128 + tx*8 + 4]);
                        float a[8] = {a0.x,a0.y,a0.z,a0.w,a1.x,a1.y,a1.z,a1.w};
                        float b[8] = {b0.x,b0.y,b0.z,b0.w,b1.x,b1.y,b1.z,b1.w};
                        #pragma unroll
                        for (int r = 0; r < 8; r++)
                            #pragma unroll
                            for (int c = 0; c < 8; c++)
                                acc[r][c] += a[r]*b[c];
                    }
                    __syncthreads();
                }

                float* Gt = (part == 0) ? d_G : d_Gx + (size_t)(part-1)*KSROWS*GC;
                #pragma unroll
                for (int rr = 0; rr < 8; rr++) {
                    int lr = ty*8 + rr;
                    if (lr < rows_t) {
                        float* gp = Gt + (size_t)(r0 + lr)*GC + jt*128 + tx*8;
                        *reinterpret_cast<float4*>(gp)     = make_float4(acc[rr][0],acc[rr][1],acc[rr][2],acc[rr][3]);
                        *reinterpret_cast<float4*>(gp + 4) = make_float4(acc[rr][4],acc[rr][5],acc[rr][6],acc[rr][7]);
                    }
                }
            } else {
                int ty = tid >> 5, tx = tid & 31;
                float acc[8][4];
                #pragma unroll
                for (int r = 0; r < 8; r++)
                    #pragma unroll
                    for (int c = 0; c < 4; c++) acc[r][c] = 0.f;
                int lmA = tid & 63, khA = (tid >> 6) * 4;
                int jloc = tid >> 1;
                int jB = jt*128 + jloc, kqB = (tid & 1) * 8;

                for (int kc = kbeg; kc < kbeg + klen; kc += 16) {
                    const float* p = (kc < HID) ? s_pl[lmA] : s_ph[lmA];
                    int ko = (kc < HID) ? kc : kc - HID;
                    float4 v0 = make_float4(0.f,0.f,0.f,0.f);
                    if (p) v0 = *reinterpret_cast<const float4*>(p + ko + khA);
                    As[(khA+0)*128 + lmA] = v0.x; As[(khA+1)*128 + lmA] = v0.y;
                    As[(khA+2)*128 + lmA] = v0.z; As[(khA+3)*128 + lmA] = v0.w;

                    const float* wp = d_Wsc + (size_t)jB * KTOT + kc + kqB;
                    float4 w0 = *reinterpret_cast<const float4*>(wp);
                    float4 w1 = *reinterpret_cast<const float4*>(wp + 4);
                    Bs[(kqB+0)*128 + jloc] = w0.x; Bs[(kqB+1)*128 + jloc] = w0.y;
                    Bs[(kqB+2)*128 + jloc] = w0.z; Bs[(kqB+3)*128 + jloc] = w0.w;
                    Bs[(kqB+4)*128 + jloc] = w1.x; Bs[(kqB+5)*128 + jloc] = w1.y;
                    Bs[(kqB+6)*128 + jloc] = w1.z; Bs[(kqB+7)*128 + jloc] = w1.w;
                    __syncthreads();
                    #pragma unroll
                    for (int k = 0; k < 16; k++) {
                        float4 a0 = *reinterpret_cast<const float4*>(&As[k*128 + ty*8]);
                        float4 a1 = *reinterpret_cast<const float4*>(&As[k*128 + ty*8 + 4]);
                        float4 b0 = *reinterpret_cast<const float4*>(&Bs[k*128 + tx*4]);
                        float a[8] = {a0.x,a0.y,a0.z,a0.w,a1.x,a1.y,a1.z,a1.w};
                        float b[4] = {b0.x,b0.y,b0.z,b0.w};
                        #pragma unroll
                        for (int r = 0; r < 8; r++)
                            #pragma unroll
                            for (int c = 0; c < 4; c++)
                                acc[r][c] += a[r]*b[c];
                    }
                    __syncthreads();
                }

                float* Gt = (part == 0) ? d_G : d_Gx + (size_t)(part-1)*KSROWS*GC;
                #pragma unroll
                for (int rr = 0; rr < 8; rr++) {
                    int lr = ty*8 + rr;
                    if (lr < rows_t) {
                        float* gp = Gt + (size_t)(r0 + lr)*GC + jt*128 + tx*4;
                        *reinterpret_cast<float4*>(gp) = make_float4(acc[rr][0],acc[rr][1],acc[rr][2],acc[rr][3]);
                    }
                }
            }
        }

        gbar();

        // gate phase: one warp per row
        int gwid = bid * (NTHR/32) + wid;
        int nwarp = GRID * (NTHR/32);
        for (int r = gwid; r < rows; r += nwarp) {
            int node = (r < nb) ? d_listB[w*MAXW + r] : d_listC[w*MAXW + (r - nb)];
            int pi = prev_idx[node];
            const float* cxp = (pi >= 0) ? d_C + (size_t)pi*HID : 0;
            const float* ccp = leaf_mask[node] ? d_LC + (size_t)node*HID
                                               : d_C + (size_t)child_idx[node]*HID;
            const float* gr = d_G + (size_t)r*GC;
            for (int j = lane; j < HID; j += 32) {
                float gi = gr[j], go = gr[HID + j], gf = gr[2*HID + j];
                for (int p = 1; p < ks; p++) {
                    const float* gx = d_Gx + (size_t)(p-1)*KSROWS*GC + (size_t)r*GC;
                    gi += gx[j]; go += gx[HID + j]; gf += gx[2*HID + j];
                }
                gi += d_bsc[j]; go += d_bsc[HID + j]; gf += d_bsc[2*HID + j];
                float cx = cxp ? cxp[j] : 0.f;
                float cc = ccp[j];
                float si = 1.f/(1.f + expf(-gi));
                float so = 1.f/(1.f + expf(-go));
                float sf = 1.f/(1.f + expf(-gf));
                float cell = sf*cx + si*cc;
                d_C[(size_t)node*HID + j] = cell;
                d_H[(size_t)node*HID + j] = so * tanhf(cell);
            }
            __syncwarp();
            if (lane == 0) {
                int ns = d_nextsib[node];
                if (ns >= 0 && atomicSub(&d_deps[ns], 1) == 1) {
                    int s = atomicAdd(&d_nb[w+1], 1);
                    if (s < MAXW) d_listB[(w+1)*MAXW + s] = ns;
                }
                int pp = d_parlast[node];
                if (pp >= 0 && atomicSub(&d_deps[pp], 1) == 1) {
                    if (prev_idx[pp] >= 0) {
                        int s = atomicAdd(&d_nb[w+1], 1);
                        if (s < MAXW) d_listB[(w+1)*MAXW + s] = pp;
                    } else {
                        int s = atomicAdd(&d_nc[w+1], 1);
                        if (s < MAXW) d_listC[(w+1)*MAXW + s] = pp;
                    }
                }
            }
        }
    }
}

// ---------------- launch ----------------
extern "C" void kernel_launch(void* const* d_in, const int* in_sizes, int n_in,
                              void* d_out, int out_size) {
    const int* leaf_mask = (const int*)d_in[0];
    const int* word      = (const int*)d_in[1];
    const int* child_idx = (const int*)d_in[2];
    const int* prev_idx  = (const int*)d_in[3];
    const float* emb = (const float*)d_in[4];
    const float* Wx  = (const float*)d_in[5];
    const float* bx  = (const float*)d_in[6];
    // d_in[7] = Wh unused (encode_h(0) contributes only bh)
    const float* bh  = (const float*)d_in[8];
    const float* Ws  = (const float*)d_in[9];
    const float* bs  = (const float*)d_in[10];
    const float* Wc  = (const float*)d_in[11];
    const float* bc  = (const float*)d_in[12];

    prep1<<<1024, 256>>>(Ws, Wc, bs, bc);
    prep2<<<(NNODE + 255)/256, 256>>>(leaf_mask, child_idx, prev_idx);
    leaf_kernel<<<dim3((NNODE + LBM - 1)/LBM, 12), NTHR>>>(word, emb, Wx, bx, bh);
    persist_kernel<<<GRID, NTHR>>>(leaf_mask, child_idx, prev_idx);
    copyout_kernel<<<3, 256>>>((float*)d_out, out_size);
}

// round 14
// speedup vs baseline: 1.9175x; 1.0020x over previous
#include <cuda_runtime.h>
#include <math.h>

#define NNODE 4095
#define HID   768
#define GC    2304      // 3*HID gate columns
#define KTOT  1536      // [hx | hc]
#define NWAVE 34
#define MAXW  1280
#define GRID  148
#define PTHR  512       // persistent kernel threads (16 warps/SM)
#define KSROWS 512

// leaf-kernel tile params (unchanged engine)
#define LTHR  256
#define LBM   64
#define LBK   16
#define LBNG  64
#define LBN   192
#define LAP   (LBM+4)

// ---------------- f32x2 packed-FMA helpers ----------------
#define FMA_F32X2(acc, a, b) \
    asm("fma.rn.f32x2 %0, %1, %2, %0;" : "+l"(acc) : "l"(a), "l"(b))
#define PACK_DUP_F32X2(out, v) do { \
    unsigned _u = __float_as_uint(v); \
    asm("mov.b64 %0, {%1, %2};" : "=l"(out) : "r"(_u), "r"(_u)); } while (0)
#define UNPACK_F32X2_F(lo, hi, v) do { \
    unsigned _lu, _hu; \
    asm("mov.b64 {%0, %1}, %2;" : "=r"(_lu), "=r"(_hu) : "l"(v)); \
    lo = __uint_as_float(_lu); hi = __uint_as_float(_hu); } while (0)

// ---------------- device scratch ----------------
__device__ float d_H[NNODE*HID];
__device__ float d_C[NNODE*HID];
__device__ float d_LH[NNODE*HID];
__device__ float d_LC[NNODE*HID];
__device__ float d_Wsc[(size_t)GC*KTOT];   // [2304][1536]: k<768 -> Ws, k>=768 -> Wc
__device__ float d_bsc[GC];
__device__ float d_G[(size_t)MAXW*GC];
__device__ float d_Gx[(size_t)7*KSROWS*GC];
__device__ int   d_listB[NWAVE*MAXW];
__device__ int   d_listC[NWAVE*MAXW];
__device__ int   d_nb[NWAVE];
__device__ int   d_nc[NWAVE];
__device__ int   d_deps[NNODE];
__device__ int   d_nextsib[NNODE];
__device__ int   d_parlast[NNODE];
__device__ int   d_leafarr[NNODE];
__device__ int   d_nleaf;
__device__ unsigned g_cnt;
__device__ volatile unsigned g_gen;

// ---------------- grid barrier ----------------
__device__ __forceinline__ void gbar() {
    __syncthreads();
    if (threadIdx.x == 0) {
        unsigned g = g_gen;
        __threadfence();
        if (atomicAdd(&g_cnt, 1u) == GRID - 1) {
            g_cnt = 0;
            __threadfence();
            g_gen = g + 1;
        } else {
            while (g_gen == g) { __nanosleep(32); }
        }
        __threadfence();
    }
    __syncthreads();
}

// ---------------- prep kernels ----------------
__global__ void prep1(const float* __restrict__ Ws, const float* __restrict__ Wc,
                      const float* __restrict__ bs, const float* __restrict__ bc) {
    long i0 = (long)blockIdx.x * blockDim.x + threadIdx.x;
    long stride = (long)gridDim.x * blockDim.x;
    for (long t = i0; t < (long)GC * KTOT; t += stride) {
        int j = (int)(t / KTOT), k = (int)(t % KTOT);
        d_Wsc[t] = (k < HID) ? Ws[(size_t)j * HID + k] : Wc[(size_t)j * HID + (k - HID)];
    }
    for (long t = i0; t < GC; t += stride) d_bsc[t] = bs[t] + bc[t];
    for (long t = i0; t < NNODE; t += stride) { d_nextsib[t] = -1; d_parlast[t] = -1; }
    for (long t = i0; t < NWAVE; t += stride) { d_nb[t] = 0; d_nc[t] = 0; }
    if (i0 == 0) { d_nleaf = 0; g_cnt = 0; g_gen = 0; }
}

__global__ void prep2(const int* __restrict__ leaf_mask,
                      const int* __restrict__ child_idx,
                      const int* __restrict__ prev_idx) {
    int i = blockIdx.x * blockDim.x + threadIdx.x;
    if (i >= NNODE) return;
    int pi = prev_idx[i];
    int isleaf = leaf_mask[i];
    d_deps[i] = (pi >= 0 ? 1 : 0) + (isleaf ? 0 : 1);
    if (pi >= 0) d_nextsib[pi] = i;
    if (!isleaf) d_parlast[child_idx[i]] = i;
    if (isleaf) { int s = atomicAdd(&d_nleaf, 1); if (s < NNODE) d_leafarr[s] = i; }
    if (pi < 0 && isleaf) { int s = atomicAdd(&d_nc[0], 1); if (s < MAXW) d_listC[s] = i; }
}

__global__ void copyout_kernel(float* __restrict__ out, int out_size) {
    int j = blockIdx.x * blockDim.x + threadIdx.x;
    if (j < HID && j < out_size) out[j] = d_H[(size_t)(NNODE - 1) * HID + j];
}

// ---------------- leaf GEMM + gates (unchanged) ----------------
__global__ __launch_bounds__(LTHR)
void leaf_kernel(const int* __restrict__ word,
                 const float* __restrict__ emb,
                 const float* __restrict__ Wx,
                 const float* __restrict__ bx,
                 const float* __restrict__ bh)
{
    __shared__ float smem[LBK*LAP + LBK*LBN];
    float* As = smem;
    float* Bs = smem + LBK*LAP;
    __shared__ const float* s_x[LBM];
    __shared__ int s_node[LBM];

    int nl = d_nleaf;
    int base = blockIdx.x * LBM;
    if (base >= nl) return;
    int rows = min(LBM, nl - base);
    int tid = threadIdx.x;
    int jt = blockIdx.y;

    if (tid < LBM) {
        if (tid < rows) {
            int node = d_leafarr[base + tid];
            s_node[tid] = node;
            s_x[tid] = emb + (size_t)word[node] * 300;
        } else { s_node[tid] = -1; s_x[tid] = 0; }
    }
    __syncthreads();

    float acc[8][6];
    #pragma unroll
    for (int r = 0; r < 8; r++)
        #pragma unroll
        for (int c = 0; c < 6; c++) acc[r][c] = 0.f;

    int tmg = tid >> 5;
    int tng = tid & 31;
    int lm  = tid >> 2;
    int lk  = (tid & 3) * 4;

    for (int k0 = 0; k0 < 300; k0 += LBK) {
        {
            const float* rp = s_x[lm];
            #pragma unroll
            for (int j = 0; j < 4; j++) {
                int k = k0 + lk + j;
                As[(lk+j)*LAP + lm] = (rp && k < 300) ? rp[k] : 0.f;
            }
        }
        #pragma unroll
        for (int pass = 0; pass < 3; pass++) {
            int n = pass*64 + lm;
            int g = n >> 6, col = n & 63;
            int jp = (g == 0 ? 0 : (g == 1 ? HID : 3*HID)) + jt*LBNG + col;
            #pragma unroll
            for (int j = 0; j < 4; j++) {
                int k = k0 + lk + j;
                Bs[(lk+j)*LBN + n] = (k < 300) ? Wx[(size_t)jp*300 + k] : 0.f;
            }
        }
        __syncthreads();
        #pragma unroll
        for (int k = 0; k < LBK; k++) {
            float a[8], b[6];
            float4 a0 = *reinterpret_cast<const float4*>(&As[k*LAP + tmg*8]);
            float4 a1 = *reinterpret_cast<const float4*>(&As[k*LAP + tmg*8 + 4]);
            a[0]=a0.x; a[1]=a0.y; a[2]=a0.z; a[3]=a0.w;
            a[4]=a1.x; a[5]=a1.y; a[6]=a1.z; a[7]=a1.w;
            #pragma unroll
            for (int c = 0; c < 6; c++) b[c] = Bs[k*LBN + tng*6 + c];
            #pragma unroll
            for (int r = 0; r < 8; r++)
                #pragma unroll
                for (int c = 0; c < 6; c++)
                    acc[r][c] += a[r]*b[c];
        }
        __syncthreads();
    }

    float* Gs = smem;
    for (int s = 0; s < 4; s++) {
        if ((tmg >> 1) == s) {
            int rl = (tmg & 1) * 8;
            #pragma unroll
            for (int r = 0; r < 8; r++)
                #pragma unroll
                for (int c = 0; c < 6; c++)
                    Gs[(rl+r)*LBN + tng*6 + c] = acc[r][c];
        }
        __syncthreads();
        for (int it = tid; it < 16*LBNG; it += LTHR) {
            int r = it >> 6, j = it & 63, m = s*16 + r;
            if (m < rows) {
                int jg = jt*LBNG + j;
                float gi = Gs[r*LBN + j]       + bx[jg]        + bh[jg];
                float go = Gs[r*LBN + 64 + j]  + bx[HID+jg]    + bh[HID+jg];
                float gc = Gs[r*LBN + 128 + j] + bx[3*HID+jg]  + bh[3*HID+jg];
                float si = 1.f/(1.f + expf(-gi));
                float so = 1.f/(1.f + expf(-go));
                float cell = si * tanhf(gc);
                float hidv = so * tanhf(cell);
                int node = s_node[m];
                d_LC[(size_t)node*HID + jg] = cell;
                d_LH[(size_t)node*HID + jg] = hidv;
            }
        }
        __syncthreads();
    }
}

// ---------------- persistent wave kernel: f32x2 double-buffered GEMM ----------------
__global__ __launch_bounds__(PTHR, 1)
void persist_kernel(const int* __restrict__ leaf_mask,
                    const int* __restrict__ child_idx,
                    const int* __restrict__ prev_idx)
{
    __shared__ float As[2][16*128];
    __shared__ float Bs[2][16*128];
    __shared__ const float* s_pl[128];
    __shared__ const float* s_ph[128];

    int tid = threadIdx.x, bid = blockIdx.x;
    int lane = tid & 31, wid = tid >> 5;
    int ty = tid >> 5;          // 0..15: rows ty*8..+7
    int tx = tid & 31;          // cols tx*4..+3
    int mA = tid & 127;         // loader row / col
    int kq = (tid >> 7) << 2;   // loader k offset: 0,4,8,12

    for (int w = 0; w < NWAVE - 1; w++) {
        gbar();
        int nb = min(d_nb[w], MAXW), nc = min(d_nc[w], MAXW);
        int rows = nb + nc;
        if (rows == 0) break;

        int rtB = (nb + 127) >> 7, rtC = (nc + 127) >> 7;
        int tiles0 = (rtB + rtC) * 18;
        int ks = 1;
        while (ks < 8 && tiles0 * ks < 120) ks <<= 1;
        if (rows > KSROWS) ks = 1;
        int ntiles = tiles0 * ks;

        for (int t = bid; t < ntiles; t += GRID) {
            int part = t % ks; int tmp = t / ks; int jt = tmp % 18; int rt = tmp / 18;
            const int* list; int base, cnt, r0, klen, kbeg;
            if (rt < rtB) { list = d_listB + w*MAXW; base = rt << 7;        cnt = nb; r0 = base;      klen = KTOT/ks; kbeg = part*klen; }
            else          { list = d_listC + w*MAXW; base = (rt - rtB) << 7; cnt = nc; r0 = nb + base; klen = HID/ks;  kbeg = HID + part*klen; }
            int rows_t = min(128, cnt - base);

            __syncthreads();  // protect s_pl/s_ph + smem from previous tile
            if (tid < 128) {
                if (tid < rows_t) {
                    int node = list[base + tid];
                    int pi = prev_idx[node];
                    s_pl[tid] = (pi >= 0) ? d_H + (size_t)pi * HID : 0;
                    s_ph[tid] = leaf_mask[node] ? d_LH + (size_t)node * HID
                                                : d_H + (size_t)child_idx[node] * HID;
                } else { s_pl[tid] = 0; s_ph[tid] = 0; }
            }
            __syncthreads();

            const float* pl = s_pl[mA];
            const float* ph = s_ph[mA];
            const float* wrow = d_Wsc + (size_t)(jt*128 + mA) * KTOT;

            int nk = klen >> 4;
            unsigned long long acc[4][4];   // 4 m-pairs x 4 n cols
            #pragma unroll
            for (int i = 0; i < 4; i++)
                #pragma unroll
                for (int j = 0; j < 4; j++) acc[i][j] = 0ULL;

            // prologue: load k-tile 0 into regs, stage to buffer 0
            float4 av, bv;
            {
                int kc = kbeg;
                const float* p = (kc < HID) ? pl : ph;
                int ko = (kc < HID) ? kc : kc - HID;
                av = p ? *reinterpret_cast<const float4*>(p + ko + kq)
                       : make_float4(0.f, 0.f, 0.f, 0.f);
                bv = *reinterpret_cast<const float4*>(wrow + kc + kq);
            }
            As[0][(kq+0)*128 + mA] = av.x; As[0][(kq+1)*128 + mA] = av.y;
            As[0][(kq+2)*128 + mA] = av.z; As[0][(kq+3)*128 + mA] = av.w;
            Bs[0][(kq+0)*128 + mA] = bv.x; Bs[0][(kq+1)*128 + mA] = bv.y;
            Bs[0][(kq+2)*128 + mA] = bv.z; Bs[0][(kq+3)*128 + mA] = bv.w;
            __syncthreads();

            for (int it = 0; it < nk; it++) {
                int cur = it & 1;
                float4 nav, nbv;
                if (it + 1 < nk) {
                    int kc = kbeg + ((it + 1) << 4);
                    const float* p = (kc < HID) ? pl : ph;
                    int ko = (kc < HID) ? kc : kc - HID;
                    nav = p ? *reinterpret_cast<const float4*>(p + ko + kq)
                            : make_float4(0.f, 0.f, 0.f, 0.f);
                    nbv = *reinterpret_cast<const float4*>(wrow + kc + kq);
                }
                const float* Ac = As[cur];
                const float* Bc = Bs[cur];
                #pragma unroll
                for (int k = 0; k < 16; k++) {
                    ulonglong2 ap0 = *reinterpret_cast<const ulonglong2*>(Ac + k*128 + ty*8);
                    ulonglong2 ap1 = *reinterpret_cast<const ulonglong2*>(Ac + k*128 + ty*8 + 4);
                    float4 b = *reinterpret_cast<const float4*>(Bc + k*128 + tx*4);
                    unsigned long long bb0, bb1, bb2, bb3;
                    PACK_DUP_F32X2(bb0, b.x);
                    PACK_DUP_F32X2(bb1, b.y);
                    PACK_DUP_F32X2(bb2, b.z);
                    PACK_DUP_F32X2(bb3, b.w);
                    FMA_F32X2(acc[0][0], ap0.x, bb0); FMA_F32X2(acc[0][1], ap0.x, bb1);
                    FMA_F32X2(acc[0][2], ap0.x, bb2); FMA_F32X2(acc[0][3], ap0.x, bb3);
                    FMA_F32X2(acc[1][0], ap0.y, bb0); FMA_F32X2(acc[1][1], ap0.y, bb1);
                    FMA_F32X2(acc[1][2], ap0.y, bb2); FMA_F32X2(acc[1][3], ap0.y, bb3);
                    FMA_F32X2(acc[2][0], ap1.x, bb0); FMA_F32X2(acc[2][1], ap1.x, bb1);
                    FMA_F32X2(acc[2][2], ap1.x, bb2); FMA_F32X2(acc[2][3], ap1.x, bb3);
                    FMA_F32X2(acc[3][0], ap1.y, bb0); FMA_F32X2(acc[3][1], ap1.y, bb1);
                    FMA_F32X2(acc[3][2], ap1.y, bb2); FMA_F32X2(acc[3][3], ap1.y, bb3);
                }
                if (it + 1 < nk) {
                    int nxt = cur ^ 1;
                    As[nxt][(kq+0)*128 + mA] = nav.x; As[nxt][(kq+1)*128 + mA] = nav.y;
                    As[nxt][(kq+2)*128 + mA] = nav.z; As[nxt][(kq+3)*128 + mA] = nav.w;
                    Bs[nxt][(kq+0)*128 + mA] = nbv.x; Bs[nxt][(kq+1)*128 + mA] = nbv.y;
                    Bs[nxt][(kq+2)*128 + mA] = nbv.z; Bs[nxt][(kq+3)*128 + mA] = nbv.w;
                    __syncthreads();
                }
            }

            // epilogue: unpack + store partial gate sums
            float* Gt = (part == 0) ? d_G : d_Gx + (size_t)(part-1)*KSROWS*GC;
            #pragma unroll
            for (int mp = 0; mp < 4; mp++) {
                float lo0, hi0, lo1, hi1, lo2, hi2, lo3, hi3;
                UNPACK_F32X2_F(lo0, hi0, acc[mp][0]);
                UNPACK_F32X2_F(lo1, hi1, acc[mp][1]);
                UNPACK_F32X2_F(lo2, hi2, acc[mp][2]);
                UNPACK_F32X2_F(lo3, hi3, acc[mp][3]);
                int lr0 = ty*8 + 2*mp, lr1 = lr0 + 1;
                if (lr0 < rows_t)
                    *reinterpret_cast<float4*>(Gt + (size_t)(r0 + lr0)*GC + jt*128 + tx*4)
                        = make_float4(lo0, lo1, lo2, lo3);
                if (lr1 < rows_t)
                    *reinterpret_cast<float4*>(Gt + (size_t)(r0 + lr1)*GC + jt*128 + tx*4)
                        = make_float4(hi0, hi1, hi2, hi3);
            }
        }

        gbar();

        // gate phase: one warp per row
        int gwid = bid * (PTHR/32) + wid;
        int nwarp = GRID * (PTHR/32);
        for (int r = gwid; r < rows; r += nwarp) {
            int node = (r < nb) ? d_listB[w*MAXW + r] : d_listC[w*MAXW + (r - nb)];
            int pi = prev_idx[node];
            const float* cxp = (pi >= 0) ? d_C + (size_t)pi*HID : 0;
            const float* ccp = leaf_mask[node] ? d_LC + (size_t)node*HID
                                               : d_C + (size_t)child_idx[node]*HID;
            const float* gr = d_G + (size_t)r*GC;
            for (int j = lane; j < HID; j += 32) {
                float gi = gr[j], go = gr[HID + j], gf = gr[2*HID + j];
                for (int p = 1; p < ks; p++) {
                    const float* gx = d_Gx + (size_t)(p-1)*KSROWS*GC + (size_t)r*GC;
                    gi += gx[j]; go += gx[HID + j]; gf += gx[2*HID + j];
                }
                gi += d_bsc[j]; go += d_bsc[HID + j]; gf += d_bsc[2*HID + j];
                float cx = cxp ? cxp[j] : 0.f;
                float cc = ccp[j];
                float si = 1.f/(1.f + expf(-gi));
                float so = 1.f/(1.f + expf(-go));
                float sf = 1.f/(1.f + expf(-gf));
                float cell = sf*cx + si*cc;
                d_C[(size_t)node*HID + j] = cell;
                d_H[(size_t)node*HID + j] = so * tanhf(cell);
            }
            __syncwarp();
            if (lane == 0) {
                int ns = d_nextsib[node];
                if (ns >= 0 && atomicSub(&d_deps[ns], 1) == 1) {
                    int s = atomicAdd(&d_nb[w+1], 1);
                    if (s < MAXW) d_listB[(w+1)*MAXW + s] = ns;
                }
                int pp = d_parlast[node];
                if (pp >= 0 && atomicSub(&d_deps[pp], 1) == 1) {
                    if (prev_idx[pp] >= 0) {
                        int s = atomicAdd(&d_nb[w+1], 1);
                        if (s < MAXW) d_listB[(w+1)*MAXW + s] = pp;
                    } else {
                        int s = atomicAdd(&d_nc[w+1], 1);
                        if (s < MAXW) d_listC[(w+1)*MAXW + s] = pp;
                    }
                }
            }
        }
    }
}

// ---------------- launch ----------------
extern "C" void kernel_launch(void* const* d_in, const int* in_sizes, int n_in,
                              void* d_out, int out_size) {
    const int* leaf_mask = (const int*)d_in[0];
    const int* word      = (const int*)d_in[1];
    const int* child_idx = (const int*)d_in[2];
    const int* prev_idx  = (const int*)d_in[3];
    const float* emb = (const float*)d_in[4];
    const float* Wx  = (const float*)d_in[5];
    const float* bx  = (const float*)d_in[6];
    // d_in[7] = Wh unused (encode_h(0) contributes only bh)
    const float* bh  = (const float*)d_in[8];
    const float* Ws  = (const float*)d_in[9];
    const float* bs  = (const float*)d_in[10];
    const float* Wc  = (const float*)d_in[11];
    const float* bc  = (const float*)d_in[12];

    prep1<<<1024, 256>>>(Ws, Wc, bs, bc);
    prep2<<<(NNODE + 255)/256, 256>>>(leaf_mask, child_idx, prev_idx);
    leaf_kernel<<<dim3((NNODE + LBM - 1)/LBM, 12), LTHR>>>(word, emb, Wx, bx, bh);
    persist_kernel<<<GRID, PTHR>>>(leaf_mask, child_idx, prev_idx);
    copyout_kernel<<<3, 256>>>((float*)d_out, out_size);
}